// round 3
// baseline (speedup 1.0000x reference)
#include <cuda_runtime.h>
#include <math.h>

#define Bn 128
#define Tn 1024
#define Hn 512

// ---------------------------------------------------------------------------
// Phase 1: pre[t][b][:] = X[b][t][:] @ Wx + bias   (written into d_out, [T,B,H])
// ---------------------------------------------------------------------------
__global__ __launch_bounds__(256) void gemm_xw(
    const float* __restrict__ X,    // [B*T, H] rows r = b*T + t
    const float* __restrict__ Wx,   // [H, H]
    const float* __restrict__ bias, // [H]
    float* __restrict__ out)        // [T, B, H]
{
    __shared__ float As[16][132];
    __shared__ float Bs[16][68];

    const int bm0 = blockIdx.y * 128;
    const int bn0 = blockIdx.x * 64;
    const int tid = threadIdx.x;
    const int tr  = (tid >> 4) << 3;
    const int tc  = (tid & 15) << 2;

    float acc[8][4];
#pragma unroll
    for (int i = 0; i < 8; i++)
#pragma unroll
        for (int j = 0; j < 4; j++) acc[i][j] = 0.0f;

    for (int k0 = 0; k0 < Hn; k0 += 16) {
#pragma unroll
        for (int v = 0; v < 2; v++) {
            int f   = tid + (v << 8);
            int row = f >> 2;
            int kk  = (f & 3) << 2;
            float4 a = *(const float4*)(X + (size_t)(bm0 + row) * Hn + k0 + kk);
            As[kk + 0][row] = a.x;
            As[kk + 1][row] = a.y;
            As[kk + 2][row] = a.z;
            As[kk + 3][row] = a.w;
        }
        {
            int kk  = tid >> 4;
            int col = (tid & 15) << 2;
            *(float4*)&Bs[kk][col] =
                *(const float4*)(Wx + (size_t)(k0 + kk) * Hn + bn0 + col);
        }
        __syncthreads();

#pragma unroll
        for (int kk = 0; kk < 16; kk++) {
            float4 a0 = *(const float4*)&As[kk][tr];
            float4 a1 = *(const float4*)&As[kk][tr + 4];
            float4 b0 = *(const float4*)&Bs[kk][tc];
            float av[8] = {a0.x, a0.y, a0.z, a0.w, a1.x, a1.y, a1.z, a1.w};
            float bv[4] = {b0.x, b0.y, b0.z, b0.w};
#pragma unroll
            for (int i = 0; i < 8; i++)
#pragma unroll
                for (int j = 0; j < 4; j++)
                    acc[i][j] = fmaf(av[i], bv[j], acc[i][j]);
        }
        __syncthreads();
    }

    float4 bb = *(const float4*)(bias + bn0 + tc);
#pragma unroll
    for (int i = 0; i < 8; i++) {
        int m = bm0 + tr + i;
        int b = m >> 10;
        int t = m & 1023;
        float4 o;
        o.x = acc[i][0] + bb.x;
        o.y = acc[i][1] + bb.y;
        o.z = acc[i][2] + bb.z;
        o.w = acc[i][3] + bb.w;
        *(float4*)(out + ((size_t)t * Bn + b) * Hn + bn0 + tc) = o;
    }
}

// ---------------------------------------------------------------------------
// Phase 2: cluster-of-8 persistent RNN, push-once / compute-local.
// 16 independent clusters (one per 8-row batch group). Rank rk owns columns
// [64rk, 64rk+64). Each CTA keeps a FULL local copy of its 8x512 state slice
// (double-buffered); after each step every thread pushes its one new value to
// all 8 ranks via st.shared::cluster. One cluster barrier per step.
// Inner loop: pure local SMEM, bank-conflict-free (stride 516).
// ---------------------------------------------------------------------------
#define SSTR 516                         // state row stride (floats)
#define SBUF_FLOATS (8 * SSTR)           // 4128
#define SBUF_BYTES  (SBUF_FLOATS * 4)    // 16512
#define WSTR 516                         // Whs column stride (floats)
#define WHS_FLOATS (64 * WSTR)           // 33024
#define SMEM_TOTAL_BYTES ((WHS_FLOATS + 2 * SBUF_FLOATS) * 4)  // 165120

__device__ __forceinline__ unsigned smem_u32(const void* p) {
    return (unsigned)__cvta_generic_to_shared(p);
}
__device__ __forceinline__ unsigned mapa_u32(unsigned addr, unsigned rank) {
    unsigned r;
    asm("mapa.shared::cluster.u32 %0, %1, %2;" : "=r"(r) : "r"(addr), "r"(rank));
    return r;
}
__device__ __forceinline__ void st_cluster_f32(unsigned addr, float v) {
    asm volatile("st.shared::cluster.f32 [%0], %1;" :: "r"(addr), "f"(v) : "memory");
}
#define CL_ARRIVE() asm volatile("barrier.cluster.arrive.aligned;" ::: "memory")
#define CL_WAIT()   asm volatile("barrier.cluster.wait.aligned;" ::: "memory")

__global__ __launch_bounds__(512, 1) __cluster_dims__(8, 1, 1)
void rnn_steps(const float* __restrict__ state0,  // [B, H]
               const float* __restrict__ Wh,      // [H, H]
               float* __restrict__ out)           // [T, B, H] (holds pre on entry)
{
    extern __shared__ float sm[];
    float* Whs  = sm;                   // [64][WSTR]  Wh[:, c0+c] column-major
    float* Sbuf = sm + WHS_FLOATS;      // [2][8][SSTR] full 8x512 state slice

    const int tid = threadIdx.x;
    unsigned rk;
    asm("mov.u32 %0, %%cluster_ctarank;" : "=r"(rk));
    const int rg = blockIdx.x >> 3;     // row group 0..15
    const int r0 = rg * 8;
    const int c0 = (int)rk * 64;

    // ---- one-time: Wh[:, c0:c0+64] transposed into Whs[c][k] ----
#pragma unroll 4
    for (int i = 0; i < 64; i++) {
        int f = tid + i * 512;          // 0..32767
        int k = f >> 6;                 // 0..511
        int c = f & 63;                 // coalesced gmem read
        Whs[c * WSTR + k] = Wh[(size_t)k * Hn + c0 + c];
    }

    // ---- one-time: FULL initial state rows [r0,r0+8) x [0,512) into buf 0 ----
#pragma unroll
    for (int i = 0; i < 8; i++) {
        int f = tid + i * 512;          // 0..4095
        int r = f >> 9;                 // 0..7
        int k = f & 511;                // coalesced
        Sbuf[r * SSTR + k] = state0[(size_t)(r0 + r) * Hn + k];
    }

    // ---- per-thread mapping: one output element (r, c) ----
    const int w    = tid >> 5;
    const int lane = tid & 31;
    const int r    = lane & 7;                 // 0..7
    const int c    = (w << 2) + (lane >> 3);   // 0..63  (local col)
    const int gc   = c0 + c;                   // global col

    // Destination addresses for my state value in every rank's Sbuf (buf 0)
    unsigned dst[8];
    {
        unsigned own = smem_u32(Sbuf + r * SSTR + gc);
#pragma unroll
        for (int s = 0; s < 8; s++) dst[s] = mapa_u32(own, (unsigned)s);
    }

    const float* wp = Whs + c * WSTR;
    float* op = out + (size_t)(r0 + r) * Hn + gc;

    CL_ARRIVE();                        // all init visible cluster-wide
    CL_WAIT();

    float pre = op[0];                  // prefetch pre-activation for t=0

    for (int t = 0; t < Tn; t++) {
        const float* Sc = Sbuf + (t & 1) * SBUF_FLOATS + r * SSTR;

        float a0 = 0.f, a1 = 0.f, a2 = 0.f, a3 = 0.f;
#pragma unroll 8
        for (int k = 0; k < Hn; k += 4) {
            float4 sv = *(const float4*)(Sc + k);
            float4 wv = *(const float4*)(wp + k);
            a0 = fmaf(sv.x, wv.x, a0);
            a1 = fmaf(sv.y, wv.y, a1);
            a2 = fmaf(sv.z, wv.z, a2);
            a3 = fmaf(sv.w, wv.w, a3);
        }
        const float v = tanhf(pre + ((a0 + a2) + (a1 + a3)));

        if (t != Tn - 1) {
            const unsigned noff = (unsigned)(((t + 1) & 1) * SBUF_BYTES);
#pragma unroll
            for (int s = 0; s < 8; s++)
                st_cluster_f32(dst[s] + noff, v);   // push to all ranks
            CL_ARRIVE();                             // release
            op[(size_t)t * (Bn * Hn)] = v;           // output (fire & forget)
            pre = op[(size_t)(t + 1) * (Bn * Hn)];   // prefetch under barrier
            CL_WAIT();                               // acquire
        } else {
            op[(size_t)t * (Bn * Hn)] = v;
        }
    }

    // Final cluster barrier: no CTA may exit while peers could still have
    // in-flight DSMEM stores targeting its SMEM.
    CL_ARRIVE();
    CL_WAIT();
}

extern "C" void kernel_launch(void* const* d_in, const int* in_sizes, int n_in,
                              void* d_out, int out_size)
{
    const float* X    = (const float*)d_in[0];  // inputs_tensor [B,T,H]
    const float* S0   = (const float*)d_in[1];  // state_tensor  [1,B,H]
    const float* Wx   = (const float*)d_in[2];  // [H,H]
    const float* Wh   = (const float*)d_in[3];  // [H,H]
    const float* bias = (const float*)d_in[4];  // [H]
    float* out = (float*)d_out;                 // [T,B,H]

    (void)in_sizes; (void)n_in; (void)out_size;

    cudaFuncSetAttribute(rnn_steps,
                         cudaFuncAttributeMaxDynamicSharedMemorySize,
                         SMEM_TOTAL_BYTES);

    dim3 g1(Hn / 64, (Bn * Tn) / 128);  // (8, 1024)
    gemm_xw<<<g1, 256>>>(X, Wx, bias, out);

    rnn_steps<<<128, 512, SMEM_TOTAL_BYTES>>>(S0, Wh, out);
}